// round 4
// baseline (speedup 1.0000x reference)
#include <cuda_runtime.h>
#include <math.h>

// Shapes fixed: x,y [4,3,1024,1024] f32; mask_y [4,8,1024,1024] f32. Out: 3 f32.
#define NPIX    4194304                // 4*1024*1024
#define HW4     262144                 // (H*W)/4 float4 units
#define GROUPS  1048576                // NPIX/4
#define NCLS    8
#define OVF_CAP 8192
#define NBLK    2048
#define NTHR    256
#define SLOTS   32

// ---- device-global scratch (zero-init at module load; finalize re-zeroes) ----
__device__ double g_Sx[SLOTS][NCLS];
__device__ double g_Sy[SLOTS][NCLS];
__device__ double g_cnt[SLOTS][NCLS];
__device__ double g_pow[SLOTS];
__device__ double g_sxx[SLOTS];
__device__ int    g_done;
__device__ int    g_ovf_n;
__device__ int    g_ovf_lab[OVF_CAP];
__device__ float  g_ovf_x[OVF_CAP];
__device__ float  g_ovf_y[OVF_CAP];

__device__ __forceinline__ float comp4(const float4& v, int j) {
    switch (j) { case 0: return v.x; case 1: return v.y; case 2: return v.z; default: return v.w; }
}

__global__ void __launch_bounds__(NTHR, 3)
seg_loss_kernel(const float* __restrict__ xg, const float* __restrict__ yg,
                const float* __restrict__ mg, float* __restrict__ out) {
    // ---- per-thread accumulation over exactly 2 groups (8 pixels) ----
    float sx[NCLS], sy[NCLS], cn[NCLS];
#pragma unroll
    for (int L = 0; L < NCLS; L++) { sx[L] = 0.f; sy[L] = 0.f; cn[L] = 0.f; }
    float powacc = 0.f, sqacc = 0.f;

    const float4* x4 = (const float4*)xg;
    const float4* y4 = (const float4*)yg;
    const float4* m4 = (const float4*)mg;

    const int tid0 = blockIdx.x * NTHR + threadIdx.x;

#pragma unroll
    for (int it = 0; it < 2; it++) {
        int g  = tid0 + it * (NBLK * NTHR);      // NBLK*NTHR*2 == GROUPS exactly
        int b  = g >> 18;                        // g / HW4
        int hw = g & (HW4 - 1);

        // 8 mask planes front-batched (MLP); x/y folded into running sums (low regs)
        float4 mv[8];
#pragma unroll
        for (int c = 0; c < 8; c++) mv[c] = m4[(size_t)(b * 8 + c) * HW4 + hw];

        size_t xb = (size_t)(b * 3) * HW4 + hw;
        float4 xs0 = x4[xb], xs1 = x4[xb + HW4], xs2 = x4[xb + 2 * HW4];
        float4 ys0 = y4[xb], ys1 = y4[xb + HW4], ys2 = y4[xb + 2 * HW4];
        float4 xs, ys;
        xs.x = (xs0.x + xs1.x) + xs2.x;  xs.y = (xs0.y + xs1.y) + xs2.y;
        xs.z = (xs0.z + xs1.z) + xs2.z;  xs.w = (xs0.w + xs1.w) + xs2.w;
        ys.x = (ys0.x + ys1.x) + ys2.x;  ys.y = (ys0.y + ys1.y) + ys2.y;
        ys.z = (ys0.z + ys1.z) + ys2.z;  ys.w = (ys0.w + ys1.w) + ys2.w;

#pragma unroll
        for (int j = 0; j < 4; j++) {
            float best = comp4(mv[0], j);
            int   bi   = 0;
#pragma unroll
            for (int c = 1; c < 8; c++) {
                float v = comp4(mv[c], j);
                if (v > best) { best = v; bi = c; }
            }
            float xa = comp4(xs, j) * (1.0f / 3.0f);
            float ya = comp4(ys, j) * (1.0f / 3.0f);

            sqacc += xa * xa;

            bool xz = (xa == 0.0f), yz = (ya == 0.0f);
            if (!xz && !yz) {
                powacc += __powf(xa, ya);
            } else {
                int i = atomicAdd(&g_ovf_n, 1);
                if (i < OVF_CAP) { g_ovf_lab[i] = bi; g_ovf_x[i] = xa; g_ovf_y[i] = ya; }
            }

#pragma unroll
            for (int L = 0; L < NCLS; L++) {
                if (bi == L) { sx[L] += xa; sy[L] += ya; cn[L] += 1.0f; }
            }
        }
    }

    // ---- warp reduction ----
    const unsigned full = 0xffffffffu;
#pragma unroll
    for (int L = 0; L < NCLS; L++) {
#pragma unroll
        for (int o = 16; o > 0; o >>= 1) {
            sx[L] += __shfl_down_sync(full, sx[L], o);
            sy[L] += __shfl_down_sync(full, sy[L], o);
            cn[L] += __shfl_down_sync(full, cn[L], o);
        }
    }
#pragma unroll
    for (int o = 16; o > 0; o >>= 1) {
        powacc += __shfl_down_sync(full, powacc, o);
        sqacc  += __shfl_down_sync(full, sqacc, o);
    }

    // ---- block stage in shared, then one atomic set per block into a slot ----
    __shared__ double ssx[NCLS], ssy[NCLS], scn[NCLS], spw, ssq;
    if (threadIdx.x < NCLS) { ssx[threadIdx.x] = 0.0; ssy[threadIdx.x] = 0.0; scn[threadIdx.x] = 0.0; }
    if (threadIdx.x == NCLS) { spw = 0.0; ssq = 0.0; }
    __syncthreads();

    if ((threadIdx.x & 31) == 0) {
#pragma unroll
        for (int L = 0; L < NCLS; L++) {
            atomicAdd(&ssx[L], (double)sx[L]);
            atomicAdd(&ssy[L], (double)sy[L]);
            atomicAdd(&scn[L], (double)cn[L]);
        }
        atomicAdd(&spw, (double)powacc);
        atomicAdd(&ssq, (double)sqacc);
    }
    __syncthreads();

    int slot = blockIdx.x & (SLOTS - 1);
    if (threadIdx.x < NCLS) {
        atomicAdd(&g_Sx[slot][threadIdx.x],  ssx[threadIdx.x]);
        atomicAdd(&g_Sy[slot][threadIdx.x],  ssy[threadIdx.x]);
        atomicAdd(&g_cnt[slot][threadIdx.x], scn[threadIdx.x]);
    }
    if (threadIdx.x == NCLS) {
        atomicAdd(&g_pow[slot], spw);
        atomicAdd(&g_sxx[slot], ssq);
    }

    // ---- last block finalizes and resets ----
    __shared__ int amLast;
    __syncthreads();
    if (threadIdx.x == 0) {
        __threadfence();
        amLast = (atomicAdd(&g_done, 1) == NBLK - 1);
    }
    __syncthreads();
    if (!amLast) return;
    __threadfence();

    __shared__ double fSx[NCLS], fSy[NCLS], fcn[NCLS], fpw, fsq;
    int t = threadIdx.x;
    if (t < NCLS) {
        double a = 0.0, b2 = 0.0, c2 = 0.0;
        for (int s = 0; s < SLOTS; s++) { a += g_Sx[s][t]; b2 += g_Sy[s][t]; c2 += g_cnt[s][t]; }
        fSx[t] = a; fSy[t] = b2; fcn[t] = c2;
    } else if (t == NCLS) {
        double a = 0.0, b2 = 0.0;
        for (int s = 0; s < SLOTS; s++) { a += g_pow[s]; b2 += g_sxx[s]; }
        fpw = a; fsq = b2;
    }
    __syncthreads();

    if (t == 0) {
        const double N = (double)NPIX;
        double xra[NCLS], yra[NCLS];
#pragma unroll
        for (int L = 0; L < NCLS; L++) { xra[L] = fSx[L] / N; yra[L] = fSy[L] / N; }

        int zx[NCLS], zboth[NCLS];
#pragma unroll
        for (int L = 0; L < NCLS; L++) { zx[L] = 0; zboth[L] = 0; }
        double exc = 0.0;
        int nov = g_ovf_n; if (nov > OVF_CAP) nov = OVF_CAP;
        for (int i = 0; i < nov; i++) {
            int   lab = g_ovf_lab[i];
            float xa  = g_ovf_x[i];
            float ya  = g_ovf_y[i];
            bool  xzb = (xa == 0.0f), yzb = (ya == 0.0f);
            if (xzb) zx[lab]++;
            if (xzb && yzb)    zboth[lab]++;
            else if (xzb)      exc += pow(xra[lab], (double)ya);
            else               exc += pow((double)xa, yra[lab]);
        }

        double l1 = 0.0, l2 = 0.0, l3 = 0.0;
#pragma unroll
        for (int L = 0; L < NCLS; L++) {
            double p = pow(xra[L], yra[L]);
            l2 += p;
            l1 += (N - fcn[L] + (double)zboth[L]) * p;
            double cnz = fcn[L] - (double)zx[L];
            l3 += 2.0 * xra[L] * fSx[L] - cnz * xra[L] * xra[L];
        }
        l1 = (l1 + fpw + exc) / N;
        l3 = (fsq - l3) / N;

        out[0] = (float)l1;
        out[1] = (float)l2;
        out[2] = (float)l3;
    }
    __syncthreads();

    // reset all device state for the next (graph-replayed) call
    for (int i = t; i < SLOTS * NCLS; i += NTHR) {
        ((double*)g_Sx)[i] = 0.0; ((double*)g_Sy)[i] = 0.0; ((double*)g_cnt)[i] = 0.0;
    }
    if (t < SLOTS) { g_pow[t] = 0.0; g_sxx[t] = 0.0; }
    if (t == 0)    { g_done = 0; g_ovf_n = 0; }
}

extern "C" void kernel_launch(void* const* d_in, const int* in_sizes, int n_in,
                              void* d_out, int out_size) {
    const float* x  = (const float*)d_in[0];
    const float* y  = (const float*)d_in[1];
    const float* mk = (const float*)d_in[2];
    float* out = (float*)d_out;
    seg_loss_kernel<<<NBLK, NTHR>>>(x, y, mk, out);
}